// round 13
// baseline (speedup 1.0000x reference)
#include <cuda_runtime.h>

// max_general_2x2: reference relu chain collapses exactly to a
// 2x2 stride-2 fp32 max-pool: out = max(a,b,c,d).
//
// Input  x: (32, 64, 112, 112) fp32 (102.8 MB)
// Output  : (32, 64, 56, 56)   fp32 ( 25.7 MB)
//
// History: R4  (4xLDG.128/thread, contiguous, 6272 CTAs): 19.58us, DRAM 71.7%
//          R5  (fragmented 8xLDG): REGRESSED (L1 70%)
//          R6  (.CS hints): neutral
//          R12 (MLP=8 clean): neutral -> load depth is NOT the limiter
// R13: persistent grid-stride at exactly-resident grid (148 SMs x 8 CTAs).
// Per-iteration body identical to R4; removes wave transitions + CTA churn.

#define NC_PLANES   (32 * 64)      // 2048 planes
#define IN_W        112
#define IN_PLANE    (112 * 112)    // 12544
#define OUT_W       56
#define V4_PER_ROW  (OUT_W / 4)    // 14 float4 per output row
#define TOTAL_V4    (NC_PLANES * OUT_W * V4_PER_ROW)  // 1,605,632

#define NUM_SMS     148
#define CTAS_PER_SM 8
#define GRID_BLOCKS (NUM_SMS * CTAS_PER_SM)   // 1184
#define THREADS     256

__global__ __launch_bounds__(THREADS) void maxpool2x2_kernel(
    const float* __restrict__ in, float4* __restrict__ out)
{
    const int stride = GRID_BLOCKS * THREADS;              // 303,104
    for (int idx = blockIdx.x * THREADS + threadIdx.x;
         idx < TOTAL_V4; idx += stride)
    {
        // idx -> (plane, oh, j); j indexes a float4 (4 output cols)
        int j     = idx % V4_PER_ROW;       // 0..13
        int t     = idx / V4_PER_ROW;
        int oh    = t % OUT_W;              // 0..55
        int plane = t / OUT_W;              // 0..2047

        // Input rows 2*oh, 2*oh+1; cols 8*j .. 8*j+7. 16B aligned.
        const float4* ip0 = reinterpret_cast<const float4*>(
            in + (size_t)plane * IN_PLANE + (2 * oh) * IN_W + 8 * j);
        const float4* ip1 = reinterpret_cast<const float4*>(
            reinterpret_cast<const float*>(ip0) + IN_W);

        // 4 independent LDG.128, contiguous warp footprint (== R4)
        float4 a0 = ip0[0];
        float4 a1 = ip0[1];
        float4 b0 = ip1[0];
        float4 b1 = ip1[1];

        float4 o;
        o.x = fmaxf(fmaxf(a0.x, a0.y), fmaxf(b0.x, b0.y));
        o.y = fmaxf(fmaxf(a0.z, a0.w), fmaxf(b0.z, b0.w));
        o.z = fmaxf(fmaxf(a1.x, a1.y), fmaxf(b1.x, b1.y));
        o.w = fmaxf(fmaxf(a1.z, a1.w), fmaxf(b1.z, b1.w));

        out[idx] = o;
    }
}

extern "C" void kernel_launch(void* const* d_in, const int* in_sizes, int n_in,
                              void* d_out, int out_size)
{
    const float* x = (const float*)d_in[0];
    float4* out = (float4*)d_out;
    maxpool2x2_kernel<<<GRID_BLOCKS, THREADS>>>(x, out);
}

// round 16
// speedup vs baseline: 1.0195x; 1.0195x over previous
#include <cuda_runtime.h>

// max_general_2x2: reference relu chain collapses exactly to a
// 2x2 stride-2 fp32 max-pool: out = max(a,b,c,d).
//
// Input  x: (32, 64, 112, 112) fp32 (102.8 MB)
// Output  : (32, 64, 56, 56)   fp32 ( 25.7 MB)
//
// R16 = R12 final-form body (8x contiguous LDG.128/thread; best banked
// harness 23.008us) with the one never-tested knob: block size 256->512.
// Ledger: contiguity load-bearing (R5); .CS neutral (R6); MLP depth
// neutral (R12); persistent grid worse (R13). DRAM plateau 66-72%.

#define NC_PLANES   (32 * 64)      // 2048 planes
#define IN_W        112
#define IN_PLANE    (112 * 112)    // 12544
#define OUT_W       56
#define V4_PER_ROW  (OUT_W / 4)    // 14 float4 per output row
#define TOTAL_V4    (NC_PLANES * OUT_W * V4_PER_ROW)  // 1,605,632
#define HALF_V4     (TOTAL_V4 / 2)                    //   802,816
#define THREADS     512

__global__ __launch_bounds__(THREADS) void maxpool2x2_kernel(
    const float* __restrict__ in, float4* __restrict__ out, int half)
{
    int idx = blockIdx.x * THREADS + threadIdx.x;
    if (idx >= half) return;

    // ---- chunk A: output float4 #idx ----
    int jA     = idx % V4_PER_ROW;
    int tA     = idx / V4_PER_ROW;
    int ohA    = tA % OUT_W;
    int planeA = tA / OUT_W;
    const float4* a0p = reinterpret_cast<const float4*>(
        in + (size_t)planeA * IN_PLANE + (2 * ohA) * IN_W + 8 * jA);
    const float4* a1p = reinterpret_cast<const float4*>(
        reinterpret_cast<const float*>(a0p) + IN_W);

    // ---- chunk B: output float4 #(idx + half) ----
    int idxB   = idx + half;
    int jB     = idxB % V4_PER_ROW;
    int tB     = idxB / V4_PER_ROW;
    int ohB    = tB % OUT_W;
    int planeB = tB / OUT_W;
    const float4* b0p = reinterpret_cast<const float4*>(
        in + (size_t)planeB * IN_PLANE + (2 * ohB) * IN_W + 8 * jB);
    const float4* b1p = reinterpret_cast<const float4*>(
        reinterpret_cast<const float*>(b0p) + IN_W);

    // 8 independent LDG.128, front-batched; each group of 4 has the
    // contiguous warp footprint validated in R4 (L1 stays ~41%).
    float4 a0 = a0p[0];
    float4 a1 = a0p[1];
    float4 a2 = a1p[0];
    float4 a3 = a1p[1];
    float4 b0 = b0p[0];
    float4 b1 = b0p[1];
    float4 b2 = b1p[0];
    float4 b3 = b1p[1];

    float4 oA, oB;
    oA.x = fmaxf(fmaxf(a0.x, a0.y), fmaxf(a2.x, a2.y));
    oA.y = fmaxf(fmaxf(a0.z, a0.w), fmaxf(a2.z, a2.w));
    oA.z = fmaxf(fmaxf(a1.x, a1.y), fmaxf(a3.x, a3.y));
    oA.w = fmaxf(fmaxf(a1.z, a1.w), fmaxf(a3.z, a3.w));
    oB.x = fmaxf(fmaxf(b0.x, b0.y), fmaxf(b2.x, b2.y));
    oB.y = fmaxf(fmaxf(b0.z, b0.w), fmaxf(b2.z, b2.w));
    oB.z = fmaxf(fmaxf(b1.x, b1.y), fmaxf(b3.x, b3.y));
    oB.w = fmaxf(fmaxf(b1.z, b1.w), fmaxf(b3.z, b3.w));

    out[idx]        = oA;
    out[idx + half] = oB;
}

extern "C" void kernel_launch(void* const* d_in, const int* in_sizes, int n_in,
                              void* d_out, int out_size)
{
    const float* x = (const float*)d_in[0];
    float4* out = (float4*)d_out;

    const int half = HALF_V4;               // 802,816 threads
    const int blocks = (half + THREADS - 1) / THREADS;  // 1568
    maxpool2x2_kernel<<<blocks, THREADS>>>(x, out, half);
}

// round 17
// speedup vs baseline: 1.0889x; 1.0681x over previous
#include <cuda_runtime.h>

// max_general_2x2: reference relu chain collapses exactly to a
// 2x2 stride-2 fp32 max-pool: out = max(a,b,c,d).
//
// Input  x: (32, 64, 112, 112) fp32 (102.8 MB)
// Output  : (32, 64, 56, 56)   fp32 ( 25.7 MB)
//
// R17 = R12 body (8x contiguous LDG.128/thread, best harness 23.008us)
// with the last untested block size: 128 threads (sweep 128/256/512).
// Ledger: contiguity load-bearing (R5); .CS neutral (R6); MLP depth
// neutral (R12); persistent grid worse (R13); 512-thr neutral/worse (R16).
// DRAM plateau 66-72% => HBM mixed-stream roofline.

#define NC_PLANES   (32 * 64)      // 2048 planes
#define IN_W        112
#define IN_PLANE    (112 * 112)    // 12544
#define OUT_W       56
#define V4_PER_ROW  (OUT_W / 4)    // 14 float4 per output row
#define TOTAL_V4    (NC_PLANES * OUT_W * V4_PER_ROW)  // 1,605,632
#define HALF_V4     (TOTAL_V4 / 2)                    //   802,816
#define THREADS     128

__global__ __launch_bounds__(THREADS) void maxpool2x2_kernel(
    const float* __restrict__ in, float4* __restrict__ out, int half)
{
    int idx = blockIdx.x * THREADS + threadIdx.x;
    if (idx >= half) return;

    // ---- chunk A: output float4 #idx ----
    int jA     = idx % V4_PER_ROW;
    int tA     = idx / V4_PER_ROW;
    int ohA    = tA % OUT_W;
    int planeA = tA / OUT_W;
    const float4* a0p = reinterpret_cast<const float4*>(
        in + (size_t)planeA * IN_PLANE + (2 * ohA) * IN_W + 8 * jA);
    const float4* a1p = reinterpret_cast<const float4*>(
        reinterpret_cast<const float*>(a0p) + IN_W);

    // ---- chunk B: output float4 #(idx + half) ----
    int idxB   = idx + half;
    int jB     = idxB % V4_PER_ROW;
    int tB     = idxB / V4_PER_ROW;
    int ohB    = tB % OUT_W;
    int planeB = tB / OUT_W;
    const float4* b0p = reinterpret_cast<const float4*>(
        in + (size_t)planeB * IN_PLANE + (2 * ohB) * IN_W + 8 * jB);
    const float4* b1p = reinterpret_cast<const float4*>(
        reinterpret_cast<const float*>(b0p) + IN_W);

    // 8 independent LDG.128, front-batched; each group of 4 has the
    // contiguous warp footprint validated in R4 (L1 stays ~41%).
    float4 a0 = a0p[0];
    float4 a1 = a0p[1];
    float4 a2 = a1p[0];
    float4 a3 = a1p[1];
    float4 b0 = b0p[0];
    float4 b1 = b0p[1];
    float4 b2 = b1p[0];
    float4 b3 = b1p[1];

    float4 oA, oB;
    oA.x = fmaxf(fmaxf(a0.x, a0.y), fmaxf(a2.x, a2.y));
    oA.y = fmaxf(fmaxf(a0.z, a0.w), fmaxf(a2.z, a2.w));
    oA.z = fmaxf(fmaxf(a1.x, a1.y), fmaxf(a3.x, a3.y));
    oA.w = fmaxf(fmaxf(a1.z, a1.w), fmaxf(a3.z, a3.w));
    oB.x = fmaxf(fmaxf(b0.x, b0.y), fmaxf(b2.x, b2.y));
    oB.y = fmaxf(fmaxf(b0.z, b0.w), fmaxf(b2.z, b2.w));
    oB.z = fmaxf(fmaxf(b1.x, b1.y), fmaxf(b3.x, b3.y));
    oB.w = fmaxf(fmaxf(b1.z, b1.w), fmaxf(b3.z, b3.w));

    out[idx]        = oA;
    out[idx + half] = oB;
}

extern "C" void kernel_launch(void* const* d_in, const int* in_sizes, int n_in,
                              void* d_out, int out_size)
{
    const float* x = (const float*)d_in[0];
    float4* out = (float4*)d_out;

    const int half = HALF_V4;               // 802,816 threads
    const int blocks = (half + THREADS - 1) / THREADS;  // 6272
    maxpool2x2_kernel<<<blocks, THREADS>>>(x, out, half);
}